// round 5
// baseline (speedup 1.0000x reference)
#include <cuda_runtime.h>
#include <math.h>

// Shapes (fixed by the problem)
#define Bc   16
#define Hc   32
#define Dh   128
#define HALF 64
#define NTHREADS 256
#define NWARPS   8
#define UNROLL   4
#define CHUNKS   4          // split-KV factor
#define CHUNK    1024       // ceil(4095 / 4)
#define NBH      (Bc * Hc)  // 512

// Split-KV partial results (allocation-free scratch)
__device__ float g_m[NBH * CHUNKS];
__device__ float g_l[NBH * CHUNKS];
__device__ float g_acc[NBH * CHUNKS][Dh];

// ---------------------------------------------------------------------------
// Kernel 1: each CTA streams one (b, h, chunk) slice of the KV cache and
// writes an un-normalized flash-attention partial (m, l, acc[128]).
// The new token (j == past) is handled entirely in the combine kernel,
// so this loop is pure clamped streaming with no special cases.
// ---------------------------------------------------------------------------
__global__ __launch_bounds__(NTHREADS, 4)
void attn_partial_kernel(const float* __restrict__ q,
                         const float* __restrict__ cache_k,
                         const float* __restrict__ cache_v,
                         int past)
{
    const int bh   = blockIdx.x >> 2;          // (b*H + h)
    const int c    = blockIdx.x & (CHUNKS - 1);
    const int b    = bh / Hc;
    const int h    = bh % Hc;
    const int tid  = threadIdx.x;
    const int wid  = tid >> 5;
    const int lane = tid & 31;

    __shared__ float s_q[Dh];
    __shared__ float s_m[NWARPS];
    __shared__ float s_l[NWARPS];
    __shared__ float s_acc[NWARPS][Dh];

    // ---- RoPE-rotate q for this (b,h) (position = past_len) ----
    const float* qp = q + (size_t)(b * Hc + h) * Dh;
    if (tid < Dh) {
        const int d = tid;
        const int i = (d < HALF) ? d : d - HALF;
        double inv = pow(10000.0, -(double)i / (double)HALF);
        double ang = (double)past * inv;
        double cd, sd;
        sincos(ang, &sd, &cd);
        const float cc = (float)cd, ss = (float)sd;
        s_q[d] = (d < HALF) ? qp[d] * cc - qp[d + HALF] * ss
                            : qp[d] * cc + qp[d - HALF] * ss;
    }
    __syncthreads();

    const float4 q4 = *reinterpret_cast<const float4*>(&s_q[lane * 4]);
    const float scale = rsqrtf((float)Dh);

    const size_t rowstride = (size_t)Hc * Dh;
    const float* ck = cache_k + ((size_t)b * past * Hc + h) * Dh;
    const float* cv = cache_v + ((size_t)b * past * Hc + h) * Dh;

    const int start = c * CHUNK;
    const int end   = min(start + CHUNK, past);

    float m = -INFINITY;
    float l = 0.0f;
    float4 acc = make_float4(0.f, 0.f, 0.f, 0.f);

    // 4 rows per warp per iteration -> 8 LDG.128 in flight per lane
    for (int base = start + wid * UNROLL; base < end; base += NWARPS * UNROLL) {
        float4 k4[UNROLL], v4[UNROLL];
        #pragma unroll
        for (int u = 0; u < UNROLL; u++) {
            const int j  = base + u;
            const int jj = min(j, past - 1);           // clamp (tail only)
            const size_t off = (size_t)jj * rowstride;
            k4[u] = *(reinterpret_cast<const float4*>(ck + off) + lane);
            v4[u] = *(reinterpret_cast<const float4*>(cv + off) + lane);
        }

        float sc[UNROLL];
        #pragma unroll
        for (int u = 0; u < UNROLL; u++) {
            float d = q4.x * k4[u].x + q4.y * k4[u].y
                    + q4.z * k4[u].z + q4.w * k4[u].w;
            #pragma unroll
            for (int o = 16; o > 0; o >>= 1)
                d += __shfl_xor_sync(0xffffffffu, d, o);
            sc[u] = (base + u < end) ? d * scale : -INFINITY;
        }

        float mnew = m;
        #pragma unroll
        for (int u = 0; u < UNROLL; u++) mnew = fmaxf(mnew, sc[u]);

        const float corr = __expf(m - mnew);
        l *= corr;
        acc.x *= corr; acc.y *= corr; acc.z *= corr; acc.w *= corr;

        #pragma unroll
        for (int u = 0; u < UNROLL; u++) {
            const float p = __expf(sc[u] - mnew);
            l += p;
            acc.x += p * v4[u].x;
            acc.y += p * v4[u].y;
            acc.z += p * v4[u].z;
            acc.w += p * v4[u].w;
        }
        m = mnew;
    }

    // ---- Cross-warp flash combine -> one partial per CTA ----
    if (lane == 0) { s_m[wid] = m; s_l[wid] = l; }
    *reinterpret_cast<float4*>(&s_acc[wid][lane * 4]) = acc;
    __syncthreads();

    const int pidx = bh * CHUNKS + c;
    if (tid < Dh) {
        float M = -INFINITY;
        #pragma unroll
        for (int w = 0; w < NWARPS; w++) M = fmaxf(M, s_m[w]);
        float L = 0.f, o = 0.f;
        #pragma unroll
        for (int w = 0; w < NWARPS; w++) {
            const float e = __expf(s_m[w] - M);
            L += s_l[w] * e;
            o += s_acc[w][tid] * e;
        }
        g_acc[pidx][tid] = o;
        if (tid == 0) { g_m[pidx] = M; g_l[pidx] = L; }
    }
}

// ---------------------------------------------------------------------------
// Kernel 2: per (b,h) fold the CHUNKS partials + the new token, normalize.
// ---------------------------------------------------------------------------
__global__ __launch_bounds__(Dh, 8)
void attn_combine_kernel(const float* __restrict__ q,
                         const float* __restrict__ k,
                         const float* __restrict__ v,
                         float* __restrict__ out,
                         int past)
{
    const int bh = blockIdx.x;
    const int b  = bh / Hc;
    const int h  = bh % Hc;
    const int d  = threadIdx.x;           // 0..127
    const int wid  = d >> 5;
    const int lane = d & 31;

    __shared__ float s_red[4];

    const float* qp = q + (size_t)(b * Hc + h) * Dh;
    const float* kp = k + (size_t)(b * Hc + h) * Dh;
    const float* vp = v + (size_t)(b * Hc + h) * Dh;

    // RoPE for q and new k at dim d
    const int i = (d < HALF) ? d : d - HALF;
    double inv = pow(10000.0, -(double)i / (double)HALF);
    double ang = (double)past * inv;
    double cd, sd;
    sincos(ang, &sd, &cd);
    const float cc = (float)cd, ss = (float)sd;
    float qr, kr;
    if (d < HALF) {
        qr = qp[d] * cc - qp[d + HALF] * ss;
        kr = kp[d] * cc - kp[d + HALF] * ss;
    } else {
        qr = qp[d] * cc + qp[d - HALF] * ss;
        kr = kp[d] * cc + kp[d - HALF] * ss;
    }

    // block-reduce q_r . k_r
    float val = qr * kr;
    #pragma unroll
    for (int o = 16; o > 0; o >>= 1)
        val += __shfl_xor_sync(0xffffffffu, val, o);
    if (lane == 0) s_red[wid] = val;
    __syncthreads();
    const float s_new = (s_red[0] + s_red[1] + s_red[2] + s_red[3])
                        * rsqrtf((float)Dh);

    // fold partials + new token
    float M = s_new;
    #pragma unroll
    for (int c = 0; c < CHUNKS; c++) M = fmaxf(M, g_m[bh * CHUNKS + c]);

    const float pn = __expf(s_new - M);
    float L = pn;
    float o = pn * vp[d];
    #pragma unroll
    for (int c = 0; c < CHUNKS; c++) {
        const int idx = bh * CHUNKS + c;
        const float e = __expf(g_m[idx] - M);
        L += g_l[idx] * e;
        o += g_acc[idx][d] * e;
    }
    out[(size_t)b * (Hc * Dh) + h * Dh + d] = o / L;
}

extern "C" void kernel_launch(void* const* d_in, const int* in_sizes, int n_in,
                              void* d_out, int out_size)
{
    const float* q       = (const float*)d_in[0];
    const float* k       = (const float*)d_in[1];
    const float* v       = (const float*)d_in[2];
    const float* cache_k = (const float*)d_in[3];
    const float* cache_v = (const float*)d_in[4];
    (void)n_in; (void)out_size;

    const int past = in_sizes[3] / (Bc * Hc * Dh);   // cache_k = [B, past, H, D]

    attn_partial_kernel<<<NBH * CHUNKS, NTHREADS>>>(q, cache_k, cache_v, past);
    attn_combine_kernel<<<NBH, Dh>>>(q, k, v, (float*)d_out, past);
}

// round 6
// speedup vs baseline: 1.1361x; 1.1361x over previous
#include <cuda_runtime.h>
#include <math.h>

// Shapes (fixed by the problem)
#define Bc   16
#define Hc   32
#define Dh   128
#define HALF 64
#define NTHREADS 256
#define NWARPS   8
#define UNROLL   4
#define CHUNKS   4          // split-KV factor
#define CHUNK    1024
#define NBH      (Bc * Hc)  // 512

// Split-KV partial results (allocation-free scratch)
__device__ float g_m[NBH * CHUNKS];
__device__ float g_l[NBH * CHUNKS];
__device__ float g_acc[NBH * CHUNKS][Dh];

// ---------------------------------------------------------------------------
// Kernel 1: blockIdx = c*NBH + bh  (chunk is the SLOW index so that a full
// resident wave covers every (b,h) on the same chunk -> concurrent CTAs touch
// complete contiguous 16KB KV rows -> DRAM row-buffer locality).
// The last chunk's CTA also handles the new RoPE'd token, so the combine
// kernel is a trivial 4-way fold.
// ---------------------------------------------------------------------------
__global__ __launch_bounds__(NTHREADS, 4)
void attn_partial_kernel(const float* __restrict__ q,
                         const float* __restrict__ k,
                         const float* __restrict__ v,
                         const float* __restrict__ cache_k,
                         const float* __restrict__ cache_v,
                         int past)
{
    const int c    = blockIdx.x >> 9;          // chunk (slow index)
    const int bh   = blockIdx.x & (NBH - 1);   // b*H + h
    const int b    = bh / Hc;
    const int h    = bh % Hc;
    const int tid  = threadIdx.x;
    const int wid  = tid >> 5;
    const int lane = tid & 31;
    const bool last = (c == CHUNKS - 1);

    __shared__ float s_q[Dh];
    __shared__ float s_k[Dh];
    __shared__ float s_v[Dh];
    __shared__ float s_m[NWARPS];
    __shared__ float s_l[NWARPS];
    __shared__ float s_acc[NWARPS][Dh];

    // ---- RoPE-rotate q (and k for the last chunk) at position = past ----
    const float* qp = q + (size_t)(b * Hc + h) * Dh;
    if (tid < Dh) {
        const int d = tid;
        const int i = (d < HALF) ? d : d - HALF;
        double inv = pow(10000.0, -(double)i / (double)HALF);
        double ang = (double)past * inv;
        double cd, sd;
        sincos(ang, &sd, &cd);
        const float cc = (float)cd, ss = (float)sd;
        s_q[d] = (d < HALF) ? qp[d] * cc - qp[d + HALF] * ss
                            : qp[d] * cc + qp[d - HALF] * ss;
        if (last) {
            const float* kp = k + (size_t)(b * Hc + h) * Dh;
            const float* vp = v + (size_t)(b * Hc + h) * Dh;
            s_k[d] = (d < HALF) ? kp[d] * cc - kp[d + HALF] * ss
                                : kp[d] * cc + kp[d - HALF] * ss;
            s_v[d] = vp[d];
        }
    }
    __syncthreads();

    const float4 q4 = *reinterpret_cast<const float4*>(&s_q[lane * 4]);
    const float scale = rsqrtf((float)Dh);

    const size_t rowstride = (size_t)Hc * Dh;
    const float* ck = cache_k + ((size_t)b * past * Hc + h) * Dh;
    const float* cv = cache_v + ((size_t)b * past * Hc + h) * Dh;

    const int start = c * CHUNK;
    const int end   = min(start + CHUNK, past);

    float m = -INFINITY;
    float l = 0.0f;
    float4 acc = make_float4(0.f, 0.f, 0.f, 0.f);

    // 4 rows per warp per iteration -> 8 LDG.128 in flight per lane
    for (int base = start + wid * UNROLL; base < end; base += NWARPS * UNROLL) {
        float4 k4[UNROLL], v4[UNROLL];
        #pragma unroll
        for (int u = 0; u < UNROLL; u++) {
            const int j  = base + u;
            const int jj = min(j, past - 1);           // clamp (tail only)
            const size_t off = (size_t)jj * rowstride;
            k4[u] = *(reinterpret_cast<const float4*>(ck + off) + lane);
            v4[u] = *(reinterpret_cast<const float4*>(cv + off) + lane);
        }

        float sc[UNROLL];
        #pragma unroll
        for (int u = 0; u < UNROLL; u++) {
            float d = q4.x * k4[u].x + q4.y * k4[u].y
                    + q4.z * k4[u].z + q4.w * k4[u].w;
            #pragma unroll
            for (int o = 16; o > 0; o >>= 1)
                d += __shfl_xor_sync(0xffffffffu, d, o);
            sc[u] = (base + u < end) ? d * scale : -INFINITY;
        }

        float mnew = m;
        #pragma unroll
        for (int u = 0; u < UNROLL; u++) mnew = fmaxf(mnew, sc[u]);

        const float corr = __expf(m - mnew);
        l *= corr;
        acc.x *= corr; acc.y *= corr; acc.z *= corr; acc.w *= corr;

        #pragma unroll
        for (int u = 0; u < UNROLL; u++) {
            const float p = __expf(sc[u] - mnew);
            l += p;
            acc.x += p * v4[u].x;
            acc.y += p * v4[u].y;
            acc.z += p * v4[u].z;
            acc.w += p * v4[u].w;
        }
        m = mnew;
    }

    // ---- New token (j == past): handled by warp 0 of the last chunk ----
    if (last && wid == 0) {
        const float4 kn = *(reinterpret_cast<const float4*>(s_k) + lane);
        const float4 vn = *(reinterpret_cast<const float4*>(s_v) + lane);
        float d = q4.x * kn.x + q4.y * kn.y + q4.z * kn.z + q4.w * kn.w;
        #pragma unroll
        for (int o = 16; o > 0; o >>= 1)
            d += __shfl_xor_sync(0xffffffffu, d, o);
        const float sc = d * scale;
        const float mnew = fmaxf(m, sc);
        const float corr = __expf(m - mnew);
        const float p    = __expf(sc - mnew);
        l = l * corr + p;
        acc.x = acc.x * corr + p * vn.x;
        acc.y = acc.y * corr + p * vn.y;
        acc.z = acc.z * corr + p * vn.z;
        acc.w = acc.w * corr + p * vn.w;
        m = mnew;
    }

    // ---- Cross-warp flash combine -> one partial per CTA ----
    if (lane == 0) { s_m[wid] = m; s_l[wid] = l; }
    *reinterpret_cast<float4*>(&s_acc[wid][lane * 4]) = acc;
    __syncthreads();

    const int pidx = bh * CHUNKS + c;
    if (tid < Dh) {
        float M = -INFINITY;
        #pragma unroll
        for (int w = 0; w < NWARPS; w++) M = fmaxf(M, s_m[w]);
        float L = 0.f, o = 0.f;
        #pragma unroll
        for (int w = 0; w < NWARPS; w++) {
            const float e = __expf(s_m[w] - M);
            L += s_l[w] * e;
            o += s_acc[w][tid] * e;
        }
        g_acc[pidx][tid] = o;
        if (tid == 0) { g_m[pidx] = M; g_l[pidx] = L; }
    }
}

// ---------------------------------------------------------------------------
// Kernel 2: trivial 4-way fold of partials per (b,h). No RoPE, no DP math.
// ---------------------------------------------------------------------------
__global__ __launch_bounds__(Dh, 8)
void attn_combine_kernel(float* __restrict__ out)
{
    const int bh = blockIdx.x;
    const int d  = threadIdx.x;           // 0..127
    const int base = bh * CHUNKS;

    float m0 = g_m[base + 0], m1 = g_m[base + 1];
    float m2 = g_m[base + 2], m3 = g_m[base + 3];
    float M = fmaxf(fmaxf(m0, m1), fmaxf(m2, m3));

    const float e0 = __expf(m0 - M), e1 = __expf(m1 - M);
    const float e2 = __expf(m2 - M), e3 = __expf(m3 - M);

    const float L = g_l[base + 0] * e0 + g_l[base + 1] * e1
                  + g_l[base + 2] * e2 + g_l[base + 3] * e3;

    const float o = g_acc[base + 0][d] * e0 + g_acc[base + 1][d] * e1
                  + g_acc[base + 2][d] * e2 + g_acc[base + 3][d] * e3;

    out[(size_t)bh * Dh + d] = o / L;
}

extern "C" void kernel_launch(void* const* d_in, const int* in_sizes, int n_in,
                              void* d_out, int out_size)
{
    const float* q       = (const float*)d_in[0];
    const float* k       = (const float*)d_in[1];
    const float* v       = (const float*)d_in[2];
    const float* cache_k = (const float*)d_in[3];
    const float* cache_v = (const float*)d_in[4];
    (void)n_in; (void)out_size;

    const int past = in_sizes[3] / (Bc * Hc * Dh);   // cache_k = [B, past, H, D]

    attn_partial_kernel<<<NBH * CHUNKS, NTHREADS>>>(q, k, v, cache_k, cache_v, past);
    attn_combine_kernel<<<NBH, Dh>>>((float*)d_out);
}

// round 7
// speedup vs baseline: 1.1548x; 1.0165x over previous
#include <cuda_runtime.h>
#include <math.h>

// Shapes (fixed by the problem)
#define Bc   16
#define Hc   32
#define Dh   128
#define HALF 64
#define CHB  37            // chunks per batch: 16*37 = 592 = 2 perfect waves @ occ 2
#define NT   512           // threads per CTA (16 warps, 2 heads per warp)
#define NBH  (Bc * Hc)

// Split partials: one per (b, chunk, h)
__device__ float g_m[Bc * CHB * Hc];
__device__ float g_l[Bc * CHB * Hc];
__device__ float g_acc[Bc * CHB * Hc][Dh];

__device__ __forceinline__ float dot4(float4 a, float4 b) {
    return a.x * b.x + a.y * b.y + a.z * b.z + a.w * b.w;
}

// ---------------------------------------------------------------------------
// Kernel 1: CTA = (b, j-chunk). Processes ALL 32 heads for its j-range, so
// every j reads K[b,j,:,:] and V[b,j,:,:] = two contiguous 16KB rows ->
// purely sequential DRAM streams. Warp w owns heads {2w, 2w+1}; each
// (warp,head) keeps private flash state -> zero cross-warp reduction.
// ---------------------------------------------------------------------------
__global__ __launch_bounds__(NT, 2)
void attn_partial_kernel(const float* __restrict__ q,
                         const float* __restrict__ k,
                         const float* __restrict__ v,
                         const float* __restrict__ cache_k,
                         const float* __restrict__ cache_v,
                         int past)
{
    const int b    = blockIdx.x / CHB;
    const int c    = blockIdx.x % CHB;
    const int tid  = threadIdx.x;
    const int w    = tid >> 5;
    const int lane = tid & 31;
    const int h0   = w * 2;

    __shared__ float s_cos[HALF];
    __shared__ float s_sin[HALF];
    __shared__ float s_q[Hc * Dh];

    // ---- RoPE angles at position = past (64 DP sincos, once per CTA) ----
    if (tid < HALF) {
        double inv = pow(10000.0, -(double)tid / (double)HALF);
        double ang = (double)past * inv;
        double cd, sd;
        sincos(ang, &sd, &cd);
        s_cos[tid] = (float)cd;
        s_sin[tid] = (float)sd;
    }
    __syncthreads();

    // ---- Rotate all 32 q heads for this batch into smem ----
    const float* qb = q + (size_t)b * Hc * Dh;
    for (int idx = tid; idx < Hc * Dh; idx += NT) {
        const int d = idx & (Dh - 1);
        const float cc = s_cos[d & (HALF - 1)];
        const float ss = s_sin[d & (HALF - 1)];
        const float x  = qb[idx];
        const float y  = qb[idx ^ HALF];     // rotate-half partner (same head)
        s_q[idx] = (d < HALF) ? x * cc - y * ss : x * cc + y * ss;
    }
    __syncthreads();

    const float4 q40 = *reinterpret_cast<const float4*>(&s_q[h0 * Dh + lane * 4]);
    const float4 q41 = *reinterpret_cast<const float4*>(&s_q[(h0 + 1) * Dh + lane * 4]);
    const float scale = rsqrtf((float)Dh);

    const size_t rowelems = (size_t)Hc * Dh;                    // 4096
    const float* Kb = cache_k + (size_t)b * past * rowelems;
    const float* Vb = cache_v + (size_t)b * past * rowelems;
    const int doff = h0 * Dh + lane * 4;

    const int start = (int)(((long long)c       * past) / CHB);
    const int end   = (int)(((long long)(c + 1) * past) / CHB);

    float  m0 = -INFINITY, m1 = -INFINITY;
    float  l0 = 0.f, l1 = 0.f;
    float4 a0 = make_float4(0.f, 0.f, 0.f, 0.f);
    float4 a1 = make_float4(0.f, 0.f, 0.f, 0.f);

    for (int j = start; j < end; j++) {
        const float* Kr = Kb + (size_t)j * rowelems + doff;
        const float* Vr = Vb + (size_t)j * rowelems + doff;
        const float4 k0 = *reinterpret_cast<const float4*>(Kr);
        const float4 k1 = *reinterpret_cast<const float4*>(Kr + Dh);
        const float4 v0 = *reinterpret_cast<const float4*>(Vr);
        const float4 v1 = *reinterpret_cast<const float4*>(Vr + Dh);

        float d0 = dot4(q40, k0);
        float d1 = dot4(q41, k1);
        #pragma unroll
        for (int o = 16; o > 0; o >>= 1) {
            d0 += __shfl_xor_sync(0xffffffffu, d0, o);
            d1 += __shfl_xor_sync(0xffffffffu, d1, o);
        }
        d0 *= scale;
        d1 *= scale;

        const float n0 = fmaxf(m0, d0);
        const float n1 = fmaxf(m1, d1);
        const float c0 = __expf(m0 - n0), p0 = __expf(d0 - n0);
        const float c1 = __expf(m1 - n1), p1 = __expf(d1 - n1);
        l0 = l0 * c0 + p0;
        l1 = l1 * c1 + p1;
        a0.x = a0.x * c0 + p0 * v0.x;  a0.y = a0.y * c0 + p0 * v0.y;
        a0.z = a0.z * c0 + p0 * v0.z;  a0.w = a0.w * c0 + p0 * v0.w;
        a1.x = a1.x * c1 + p1 * v1.x;  a1.y = a1.y * c1 + p1 * v1.y;
        a1.z = a1.z * c1 + p1 * v1.z;  a1.w = a1.w * c1 + p1 * v1.w;
        m0 = n0;
        m1 = n1;
    }

    // ---- New token (j == past): folded by chunk-0 CTAs ----
    if (c == 0) {
        const int d = lane * 4;
        const int i = d & (HALF - 1);
        const float4 c4 = make_float4(s_cos[i], s_cos[i+1], s_cos[i+2], s_cos[i+3]);
        const float4 s4 = make_float4(s_sin[i], s_sin[i+1], s_sin[i+2], s_sin[i+3]);
        #pragma unroll
        for (int u = 0; u < 2; u++) {
            const int h = h0 + u;
            const float* kp = k + ((size_t)(b * Hc + h)) * Dh;
            const float* vp = v + ((size_t)(b * Hc + h)) * Dh;
            const float4 kx = *reinterpret_cast<const float4*>(kp + d);
            const float4 ko = *reinterpret_cast<const float4*>(kp + (d ^ HALF));
            const float4 vn = *reinterpret_cast<const float4*>(vp + d);
            float4 kr;
            if (d < HALF) {
                kr.x = kx.x * c4.x - ko.x * s4.x;  kr.y = kx.y * c4.y - ko.y * s4.y;
                kr.z = kx.z * c4.z - ko.z * s4.z;  kr.w = kx.w * c4.w - ko.w * s4.w;
            } else {
                kr.x = kx.x * c4.x + ko.x * s4.x;  kr.y = kx.y * c4.y + ko.y * s4.y;
                kr.z = kx.z * c4.z + ko.z * s4.z;  kr.w = kx.w * c4.w + ko.w * s4.w;
            }
            const float4 qq = u ? q41 : q40;
            float sc = dot4(qq, kr);
            #pragma unroll
            for (int o = 16; o > 0; o >>= 1)
                sc += __shfl_xor_sync(0xffffffffu, sc, o);
            sc *= scale;

            float&  m = u ? m1 : m0;
            float&  l = u ? l1 : l0;
            float4& a = u ? a1 : a0;
            const float n  = fmaxf(m, sc);
            const float cr = __expf(m - n);
            const float p  = __expf(sc - n);
            l = l * cr + p;
            a.x = a.x * cr + p * vn.x;  a.y = a.y * cr + p * vn.y;
            a.z = a.z * cr + p * vn.z;  a.w = a.w * cr + p * vn.w;
            m = n;
        }
    }

    // ---- Write partials (no cross-warp reduction needed) ----
    const int pbase = (b * CHB + c) * Hc;
    if (lane == 0) {
        g_m[pbase + h0]     = m0;  g_l[pbase + h0]     = l0;
        g_m[pbase + h0 + 1] = m1;  g_l[pbase + h0 + 1] = l1;
    }
    *reinterpret_cast<float4*>(&g_acc[pbase + h0][lane * 4])     = a0;
    *reinterpret_cast<float4*>(&g_acc[pbase + h0 + 1][lane * 4]) = a1;
}

// ---------------------------------------------------------------------------
// Kernel 2: per (b,h) fold CHB partials, normalize.
// ---------------------------------------------------------------------------
__global__ __launch_bounds__(Dh, 8)
void attn_combine_kernel(float* __restrict__ out)
{
    const int bh = blockIdx.x;
    const int b  = bh >> 5;
    const int h  = bh & (Hc - 1);
    const int d  = threadIdx.x;

    float M = -INFINITY;
    #pragma unroll
    for (int c = 0; c < CHB; c++)
        M = fmaxf(M, g_m[(b * CHB + c) * Hc + h]);

    float L = 0.f, o = 0.f;
    #pragma unroll
    for (int c = 0; c < CHB; c++) {
        const int idx = (b * CHB + c) * Hc + h;
        const float e = __expf(g_m[idx] - M);
        L += g_l[idx] * e;
        o += g_acc[idx][d] * e;
    }
    out[(size_t)bh * Dh + d] = o / L;
}

extern "C" void kernel_launch(void* const* d_in, const int* in_sizes, int n_in,
                              void* d_out, int out_size)
{
    const float* q       = (const float*)d_in[0];
    const float* k       = (const float*)d_in[1];
    const float* v       = (const float*)d_in[2];
    const float* cache_k = (const float*)d_in[3];
    const float* cache_v = (const float*)d_in[4];
    (void)n_in; (void)out_size;

    const int past = in_sizes[3] / (Bc * Hc * Dh);   // cache_k = [B, past, H, D]

    attn_partial_kernel<<<Bc * CHB, NT>>>(q, k, v, cache_k, cache_v, past);
    attn_combine_kernel<<<NBH, Dh>>>((float*)d_out);
}

// round 8
// speedup vs baseline: 1.2212x; 1.0576x over previous
#include <cuda_runtime.h>
#include <math.h>

// Shapes (fixed by the problem)
#define Bc   16
#define Hc   32
#define Dh   128
#define HALF 64
#define CHB  18            // chunks per batch: 16*18 = 288 CTAs = ONE wave @ occ 2
#define NT   512           // 16 warps, 2 heads per warp
#define NBH  (Bc * Hc)

// Scratch (allocation-free)
__device__ float g_m[Bc * CHB * Hc];
__device__ float g_l[Bc * CHB * Hc];
__device__ float g_acc[Bc * CHB * Hc][Dh];
__device__ int   g_cnt[Bc];            // zero-init; reset by folder each launch
__device__ float g_cos[HALF];
__device__ float g_sin[HALF];

__device__ __forceinline__ float dot4(float4 a, float4 b) {
    return a.x * b.x + a.y * b.y + a.z * b.z + a.w * b.w;
}

// ---------------------------------------------------------------------------
// Kernel 0: RoPE table at position = past (64 DP sincos, once per launch).
// ---------------------------------------------------------------------------
__global__ void rope_table_kernel(int past)
{
    const int i = threadIdx.x;
    if (i < HALF) {
        double inv = pow(10000.0, -(double)i / (double)HALF);
        double ang = (double)past * inv;
        double cd, sd;
        sincos(ang, &sd, &cd);
        g_cos[i] = (float)cd;
        g_sin[i] = (float)sd;
    }
}

// ---------------------------------------------------------------------------
// Kernel 1: CTA = (b, j-chunk); processes ALL 32 heads for its j-range so the
// DRAM streams are perfectly contiguous. Software-pipelined j-loop. The last
// CTA to finish per batch folds the CHB partials (L2-hot) and writes output.
// ---------------------------------------------------------------------------
__global__ __launch_bounds__(NT, 2)
void attn_kernel(const float* __restrict__ q,
                 const float* __restrict__ k,
                 const float* __restrict__ v,
                 const float* __restrict__ cache_k,
                 const float* __restrict__ cache_v,
                 float* __restrict__ out,
                 int past)
{
    const int b    = blockIdx.x / CHB;
    const int c    = blockIdx.x % CHB;
    const int tid  = threadIdx.x;
    const int w    = tid >> 5;
    const int lane = tid & 31;
    const int h0   = w * 2;

    __shared__ float s_cos[HALF];
    __shared__ float s_sin[HALF];
    __shared__ float s_q[Hc * Dh];
    __shared__ float s_e[Hc][CHB];
    __shared__ float s_L[Hc];
    __shared__ int   s_last;

    if (tid < HALF) {
        s_cos[tid] = g_cos[tid];
        s_sin[tid] = g_sin[tid];
    }
    __syncthreads();

    // ---- Rotate all 32 q heads for this batch into smem ----
    const float* qb = q + (size_t)b * Hc * Dh;
    for (int idx = tid; idx < Hc * Dh; idx += NT) {
        const int d = idx & (Dh - 1);
        const float cc = s_cos[d & (HALF - 1)];
        const float ss = s_sin[d & (HALF - 1)];
        const float x  = qb[idx];
        const float y  = qb[idx ^ HALF];
        s_q[idx] = (d < HALF) ? x * cc - y * ss : x * cc + y * ss;
    }
    __syncthreads();

    const float4 q40 = *reinterpret_cast<const float4*>(&s_q[h0 * Dh + lane * 4]);
    const float4 q41 = *reinterpret_cast<const float4*>(&s_q[(h0 + 1) * Dh + lane * 4]);
    const float scale = rsqrtf((float)Dh);

    const size_t rowelems = (size_t)Hc * Dh;                    // 4096
    const float* Kb = cache_k + (size_t)b * past * rowelems;
    const float* Vb = cache_v + (size_t)b * past * rowelems;
    const int doff = h0 * Dh + lane * 4;

    const int start = (int)(((long long)c       * past) / CHB);
    const int end   = (int)(((long long)(c + 1) * past) / CHB);

    float  m0 = -INFINITY, m1 = -INFINITY;
    float  l0 = 0.f, l1 = 0.f;
    float4 a0 = make_float4(0.f, 0.f, 0.f, 0.f);
    float4 a1 = make_float4(0.f, 0.f, 0.f, 0.f);

    // ---- Software-pipelined streaming loop ----
    {
        const float* Kr = Kb + (size_t)start * rowelems + doff;
        const float* Vr = Vb + (size_t)start * rowelems + doff;
        float4 k0 = *reinterpret_cast<const float4*>(Kr);
        float4 k1 = *reinterpret_cast<const float4*>(Kr + Dh);
        float4 v0 = *reinterpret_cast<const float4*>(Vr);
        float4 v1 = *reinterpret_cast<const float4*>(Vr + Dh);

        for (int j = start; j < end; j++) {
            // prefetch j+1 (clamped) while computing j
            const int jn = (j + 1 < end) ? j + 1 : j;
            const float* Kn = Kb + (size_t)jn * rowelems + doff;
            const float* Vn = Vb + (size_t)jn * rowelems + doff;
            const float4 k0n = *reinterpret_cast<const float4*>(Kn);
            const float4 k1n = *reinterpret_cast<const float4*>(Kn + Dh);
            const float4 v0n = *reinterpret_cast<const float4*>(Vn);
            const float4 v1n = *reinterpret_cast<const float4*>(Vn + Dh);

            float d0 = dot4(q40, k0);
            float d1 = dot4(q41, k1);
            #pragma unroll
            for (int o = 16; o > 0; o >>= 1) {
                d0 += __shfl_xor_sync(0xffffffffu, d0, o);
                d1 += __shfl_xor_sync(0xffffffffu, d1, o);
            }
            d0 *= scale;
            d1 *= scale;

            const float n0 = fmaxf(m0, d0);
            const float n1 = fmaxf(m1, d1);
            const float c0 = __expf(m0 - n0), p0 = __expf(d0 - n0);
            const float c1 = __expf(m1 - n1), p1 = __expf(d1 - n1);
            l0 = l0 * c0 + p0;
            l1 = l1 * c1 + p1;
            a0.x = a0.x * c0 + p0 * v0.x;  a0.y = a0.y * c0 + p0 * v0.y;
            a0.z = a0.z * c0 + p0 * v0.z;  a0.w = a0.w * c0 + p0 * v0.w;
            a1.x = a1.x * c1 + p1 * v1.x;  a1.y = a1.y * c1 + p1 * v1.y;
            a1.z = a1.z * c1 + p1 * v1.z;  a1.w = a1.w * c1 + p1 * v1.w;
            m0 = n0;
            m1 = n1;

            k0 = k0n; k1 = k1n; v0 = v0n; v1 = v1n;
        }
    }

    // ---- New token (j == past): folded by chunk-0 CTAs ----
    if (c == 0) {
        const int d = lane * 4;
        const int i = d & (HALF - 1);
        const float4 c4 = make_float4(s_cos[i], s_cos[i+1], s_cos[i+2], s_cos[i+3]);
        const float4 s4 = make_float4(s_sin[i], s_sin[i+1], s_sin[i+2], s_sin[i+3]);
        #pragma unroll
        for (int u = 0; u < 2; u++) {
            const int h = h0 + u;
            const float* kp = k + ((size_t)(b * Hc + h)) * Dh;
            const float* vp = v + ((size_t)(b * Hc + h)) * Dh;
            const float4 kx = *reinterpret_cast<const float4*>(kp + d);
            const float4 ko = *reinterpret_cast<const float4*>(kp + (d ^ HALF));
            const float4 vn = *reinterpret_cast<const float4*>(vp + d);
            float4 kr;
            if (d < HALF) {
                kr.x = kx.x * c4.x - ko.x * s4.x;  kr.y = kx.y * c4.y - ko.y * s4.y;
                kr.z = kx.z * c4.z - ko.z * s4.z;  kr.w = kx.w * c4.w - ko.w * s4.w;
            } else {
                kr.x = kx.x * c4.x + ko.x * s4.x;  kr.y = kx.y * c4.y + ko.y * s4.y;
                kr.z = kx.z * c4.z + ko.z * s4.z;  kr.w = kx.w * c4.w + ko.w * s4.w;
            }
            const float4 qq = u ? q41 : q40;
            float sc = dot4(qq, kr);
            #pragma unroll
            for (int o = 16; o > 0; o >>= 1)
                sc += __shfl_xor_sync(0xffffffffu, sc, o);
            sc *= scale;

            float&  mm = u ? m1 : m0;
            float&  ll = u ? l1 : l0;
            float4& aa = u ? a1 : a0;
            const float n  = fmaxf(mm, sc);
            const float cr = __expf(mm - n);
            const float p  = __expf(sc - n);
            ll = ll * cr + p;
            aa.x = aa.x * cr + p * vn.x;  aa.y = aa.y * cr + p * vn.y;
            aa.z = aa.z * cr + p * vn.z;  aa.w = aa.w * cr + p * vn.w;
            mm = n;
        }
    }

    // ---- Write partials ----
    const int pbase = (b * CHB + c) * Hc;
    if (lane == 0) {
        g_m[pbase + h0]     = m0;  g_l[pbase + h0]     = l0;
        g_m[pbase + h0 + 1] = m1;  g_l[pbase + h0 + 1] = l1;
    }
    *reinterpret_cast<float4*>(&g_acc[pbase + h0][lane * 4])     = a0;
    *reinterpret_cast<float4*>(&g_acc[pbase + h0 + 1][lane * 4]) = a1;

    // ---- Last CTA per batch folds all CHB partials (L2-hot) ----
    __threadfence();
    __syncthreads();
    if (tid == 0) {
        const int prev = atomicAdd(&g_cnt[b], 1);
        s_last = (prev == CHB - 1) ? 1 : 0;
    }
    __syncthreads();
    if (!s_last) return;
    __threadfence();

    // per-head scalars: warp 0's 32 lanes each own one head
    if (tid < Hc) {
        const int h = tid;
        float M = -INFINITY;
        #pragma unroll
        for (int cc = 0; cc < CHB; cc++)
            M = fmaxf(M, g_m[(b * CHB + cc) * Hc + h]);
        float L = 0.f;
        #pragma unroll
        for (int cc = 0; cc < CHB; cc++) {
            const float e = __expf(g_m[(b * CHB + cc) * Hc + h] - M);
            s_e[h][cc] = e;
            L += g_l[(b * CHB + cc) * Hc + h] * e;
        }
        s_L[h] = L;
    }
    __syncthreads();

    // fold acc: 32 heads x 32 float4-columns = 1024 units; 512 threads -> 2 each
    for (int unit = tid; unit < Hc * (Dh / 4); unit += NT) {
        const int h  = unit >> 5;          // head
        const int d4 = unit & 31;          // float4 column
        float4 o = make_float4(0.f, 0.f, 0.f, 0.f);
        #pragma unroll
        for (int cc = 0; cc < CHB; cc++) {
            const float4 a = *reinterpret_cast<const float4*>(
                &g_acc[(b * CHB + cc) * Hc + h][d4 * 4]);
            const float e = s_e[h][cc];
            o.x += a.x * e;  o.y += a.y * e;
            o.z += a.z * e;  o.w += a.w * e;
        }
        const float invL = 1.0f / s_L[h];
        o.x *= invL;  o.y *= invL;  o.z *= invL;  o.w *= invL;
        *reinterpret_cast<float4*>(
            &out[((size_t)b * Hc + h) * Dh + d4 * 4]) = o;
    }

    __syncthreads();
    if (tid == 0) g_cnt[b] = 0;            // reset for next graph replay
}

extern "C" void kernel_launch(void* const* d_in, const int* in_sizes, int n_in,
                              void* d_out, int out_size)
{
    const float* q       = (const float*)d_in[0];
    const float* k       = (const float*)d_in[1];
    const float* v       = (const float*)d_in[2];
    const float* cache_k = (const float*)d_in[3];
    const float* cache_v = (const float*)d_in[4];
    (void)n_in; (void)out_size;

    const int past = in_sizes[3] / (Bc * Hc * Dh);   // cache_k = [B, past, H, D]

    rope_table_kernel<<<1, HALF>>>(past);
    attn_kernel<<<Bc * CHB, NT>>>(q, k, v, cache_k, cache_v,
                                  (float*)d_out, past);
}